// round 14
// baseline (speedup 1.0000x reference)
#include <cuda_runtime.h>
#include <cuda_bf16.h>
#include <math.h>

#define BB 16
#define NN 25200
#define KPRE 1024
#define MAXDET 300
#define OUTC 89
#define UTW 16896   // upper-triangle words per batch: 32 * 528
#define APB 24      // anchors per k_score block (NN % 24 == 0 -> 1050 blocks/batch)
#define SMTAIL (UTW * 4)   // 67584 B dynamic smem for k_tail

// candidate key: [score_bits:32][(NN - anchor):15][class:7]
// g_top entry:   [score_bits:32][class:7 @bit15][anchor:15 @bit0]

// ---------------- scratch (device globals; zero-initialized at load) ----------------
__device__ unsigned           g_cnt[BB];      // zeroed inside k_tail
__device__ unsigned long long g_cand[BB*NN];
__device__ unsigned long long g_top[BB*KPRE];
__device__ float4             g_boxes[BB*KPRE];
__device__ unsigned           g_validw[BB*32];
__device__ unsigned           g_maskut[BB*UTW];
__device__ int                g_sel[BB*MAXDET];
__device__ int                g_nk[BB];
__device__ unsigned           g_flag[BB];     // sortsel done (reset in k_tail)
__device__ unsigned           g_done[BB];     // iou arrival count (reset in k_tail)

static __device__ __forceinline__ int score_bin(unsigned bits) {
    int bin = (int)(bits >> 16) - 0x3E00;
    return bin < 0 ? 0 : (bin > 511 ? 511 : bin);
}
static __device__ __forceinline__ int ut_tilestart(int t) {
    return 32 * (32*t - (t*(t-1))/2);
}

// ---------------- phase 1: dense uint4-streamed score/argmax (unchanged R13) ----------------
__global__ void k_score(const float* __restrict__ pred) {
    __shared__ float srow[APB*85];
    __shared__ unsigned long long sbuf[APB];
    __shared__ unsigned scnt;
    __shared__ unsigned sbase;
    int tid = threadIdx.x;
    int b = blockIdx.y;
    int a0 = blockIdx.x * APB;
    if (tid == 0) scnt = 0;

    const uint4* gp = (const uint4*)(pred + ((size_t)b*NN + a0) * 85);
    uint4* sp = (uint4*)srow;
    #pragma unroll
    for (int i = tid; i < 510; i += 256) sp[i] = gp[i];
    __syncthreads();

    int wid = tid >> 5, lane = tid & 31;
    #pragma unroll
    for (int k = 0; k < 3; k++) {
        int row = wid*3 + k;
        const float* rp = &srow[row*85];
        float obj = rp[4];
        if (obj > 0.4f) {
            float l0 = rp[lane];
            float l1 = rp[32 + lane];
            float l2 = (lane < 21) ? rp[64 + lane] : 0.f;
            float bv; int bi;
            if (lane >= 5) { bv = l0 * obj; bi = lane - 5; }
            else           { bv = -1.f;     bi = 127; }
            { float p = l1 * obj; if (p > bv) { bv = p; bi = 27 + lane; } }
            if (lane < 21) { float p = l2 * obj; if (p > bv) { bv = p; bi = 59 + lane; } }

            unsigned u = __float_as_uint(bv);
            unsigned mmax = __reduce_max_sync(0xffffffffu, u);
            unsigned mcls = __reduce_min_sync(0xffffffffu, (u == mmax) ? (unsigned)bi : 0xFFu);

            if (lane == 0 && __uint_as_float(mmax) > 0.4f) {
                unsigned anchor = (unsigned)(a0 + row);
                unsigned long long key = ((unsigned long long)mmax << 32)
                                       | ((unsigned long long)((unsigned)NN - anchor) << 7)
                                       | (unsigned long long)mcls;
                unsigned p = atomicAdd(&scnt, 1u);
                sbuf[p] = key;
            }
        }
    }
    __syncthreads();
    if (tid == 0 && scnt) sbase = atomicAdd(&g_cnt[b], scnt);
    __syncthreads();
    if (tid < scnt)
        g_cand[(size_t)b*NN + sbase + tid] = sbuf[tid];
}

// ---------------- phase 2: fused sortsel -> iou -> nms, per-batch pipelined ----------------
// grid (17, BB), 1024 threads, SMTAIL dynamic smem.
// smem layout (union by phase):
//   sortsel (bx==0): skA u64[1024] @0, tbuf u64[4096] @8K, hist u32[512] @40K
//   iou:             sb float4[1024] @0, sa f32[1024] @16K, tS0 @20K, tS1 @25K
//   nms (last blk):  mask u32[UTW] @0
__global__ void k_tail(const float* __restrict__ pred) {
    extern __shared__ char sraw[];
    __shared__ int sT; __shared__ unsigned sM, nA, nB;
    __shared__ int s_old;
    int b = blockIdx.y, bx = blockIdx.x, tid = threadIdx.x;

    // ======== stage A: sortsel on block x=0 ========
    if (bx == 0) {
        unsigned long long* skA  = (unsigned long long*)sraw;
        unsigned long long* tbuf = (unsigned long long*)(sraw + 8192);
        unsigned*           hist = (unsigned*)(sraw + 40960);

        skA[tid] = 0ull;
        if (tid < 512) hist[tid] = 0u;
        if (tid == 0) { nA = 0; nB = 0; }
        __syncthreads();

        unsigned nc = min(g_cnt[b], (unsigned)NN);
        const unsigned long long* cand = &g_cand[(size_t)b*NN];
        for (unsigned i = tid; i < nc; i += 1024)
            atomicAdd(&hist[score_bin((unsigned)(cand[i] >> 32))], 1u);
        __syncthreads();
        for (int off = 1; off < 512; off <<= 1) {
            unsigned v = 0;
            if (tid < 512 && tid + off < 512) v = hist[tid + off];
            __syncthreads();
            if (tid < 512) hist[tid] += v;
            __syncthreads();
        }
        if (tid < 512) {
            unsigned suf  = hist[tid];
            unsigned sufn = (tid < 511) ? hist[tid + 1] : 0u;
            if (tid == 0 && suf < (unsigned)KPRE) { sT = -1; sM = 0; }
            if (suf >= (unsigned)KPRE && sufn < (unsigned)KPRE) { sT = tid; sM = suf - sufn; }
        }
        __syncthreads();
        int T = sT;
        unsigned m = min(sM, 4096u);
        unsigned St = 32; while (St < m) St <<= 1;
        for (unsigned i = tid; i < St; i += 1024) tbuf[i] = 0ull;
        __syncthreads();
        for (unsigned i = tid; i < nc; i += 1024) {
            unsigned long long key = cand[i];
            int bin = score_bin((unsigned)(key >> 32));
            if (bin > T) {
                unsigned p = atomicAdd(&nA, 1u);
                if (p < 1024u) skA[p] = key;
            } else if (bin == T) {
                unsigned p = atomicAdd(&nB, 1u);
                if (p < 4096u) tbuf[p] = key;
            }
        }
        __syncthreads();
        if (m > 0u) {
            for (unsigned k2 = 2; k2 <= St; k2 <<= 1) {
                for (unsigned j = k2 >> 1; j > 0; j >>= 1) {
                    for (unsigned i = tid; i < St; i += 1024) {
                        unsigned ixj = i ^ j;
                        if (ixj > i) {
                            bool up = ((i & k2) == 0);
                            unsigned long long x = tbuf[i], y = tbuf[ixj];
                            bool sw = up ? (x < y) : (x > y);
                            if (sw) { tbuf[i] = y; tbuf[ixj] = x; }
                        }
                    }
                    __syncthreads();
                }
            }
            unsigned a = nA;
            unsigned needK = 1024u - a;
            if (tid < needK && tid < St) skA[a + tid] = tbuf[tid];
            __syncthreads();
        }
        for (unsigned k2 = 2; k2 <= 1024; k2 <<= 1) {
            for (unsigned j = k2 >> 1; j > 0; j >>= 1) {
                unsigned i = tid, ixj = i ^ j;
                if (ixj > i) {
                    bool up = ((i & k2) == 0);
                    unsigned long long x = skA[i], y = skA[ixj];
                    bool sw = up ? (x < y) : (x > y);
                    if (sw) { skA[i] = y; skA[ixj] = x; }
                }
                __syncthreads();
            }
        }
        {
            unsigned long long key = skA[tid];
            unsigned bits = (unsigned)(key >> 32);
            unsigned anchor = 0, cls = 0;
            if (bits) {
                anchor = (unsigned)NN - ((unsigned)(key >> 7) & 0x7FFFu);
                cls = (unsigned)key & 0x7Fu;
            }
            g_top[b*KPRE + tid] = ((unsigned long long)bits << 32) | (cls << 15) | anchor;
            float4 bx4 = make_float4(0.f, 0.f, 0.f, 0.f);
            if (bits) {
                size_t pb = ((size_t)b*NN + anchor) * 85;
                float x = pred[pb], y = pred[pb+1], w = pred[pb+2], h = pred[pb+3];
                float off = (float)cls * 4096.0f;
                bx4.x = (x - w*0.5f) + off;
                bx4.y = (y - h*0.5f) + off;
                bx4.z = (x + w*0.5f) + off;
                bx4.w = (y + h*0.5f) + off;
            }
            g_boxes[b*KPRE + tid] = bx4;
            unsigned bal = __ballot_sync(0xffffffffu, bits != 0u);
            if ((tid & 31) == 0) g_validw[b*32 + (tid >> 5)] = bal;
        }
        if (tid == 0) g_cnt[b] = 0;
        __threadfence();
        __syncthreads();
        if (tid == 0) atomicExch(&g_flag[b], 1u);   // release
    } else {
        // wait for this batch's sortsel (lower-bid producer only)
        if (tid == 0) {
            while (atomicAdd(&g_flag[b], 0u) == 0u) __nanosleep(64);
        }
        __syncthreads();
        __threadfence();                             // acquire
    }

    // ======== stage B: iou tile-pair (all 17 blocks) ========
    {
        float4*   sb  = (float4*)sraw;
        float*    sa  = (float*)(sraw + 16384);
        unsigned (*tS0)[33] = (unsigned (*)[33])(sraw + 20480);
        unsigned (*tS1)[33] = (unsigned (*)[33])(sraw + 25600);

        __syncthreads();   // smem reuse boundary (block 0: sortsel data dead)
        float4 v = g_boxes[b*KPRE + tid];
        sb[tid] = v;
        sa[tid] = (v.z - v.x) * (v.w - v.y);
        __syncthreads();

        int t0 = bx, nw0 = 32 - t0;
        int t1 = (bx >= 1 && bx <= 15) ? 32 - bx : -1;
        int nw1 = (t1 >= 0) ? 32 - t1 : 0;

        int w = tid >> 5, lane = tid & 31;
        int tile = -1, wcol = 0;
        if (w < nw0)            { tile = t0; wcol = t0 + w; }
        else if (w < nw0 + nw1) { tile = t1; wcol = t1 + (w - nw0); }

        if (tile >= 0) {
            int r = tile*32 + lane;
            float4 rb_ = sb[r];
            float  ra  = sa[r];
            unsigned bits = 0u;
            int j0 = wcol * 32;
            #pragma unroll 4
            for (int t = 0; t < 32; t++) {
                int j = j0 + t;
                float4 cb = sb[j];
                float ltx = fmaxf(rb_.x, cb.x), lty = fmaxf(rb_.y, cb.y);
                float rbx = fminf(rb_.z, cb.z), rby = fminf(rb_.w, cb.w);
                float iw = fmaxf(rbx - ltx, 0.f), ih = fmaxf(rby - lty, 0.f);
                float inter = iw * ih;
                float den = ((ra + sa[j]) - inter) + 1e-7f;
                float thr = 0.45f * den;
                bool sup;
                if (inter > thr * (1.0f + 1e-5f))       sup = true;
                else if (inter < thr * (1.0f - 1e-5f))  sup = false;
                else                                    sup = (__fdiv_rn(inter, den) > 0.45f);
                sup = sup && (j > r);
                bits |= sup ? (1u << t) : 0u;
            }
            if (tile == t0) tS0[lane][wcol - t0] = bits;
            else            tS1[lane][wcol - t1] = bits;
        }
        __syncthreads();
        {
            int ts0 = ut_tilestart(t0);
            int tot0 = 32 * nw0;
            for (int i = tid; i < tot0; i += 1024) {
                int rl = i / nw0, off = i - rl*nw0;
                g_maskut[(size_t)b*UTW + ts0 + i] = tS0[rl][off];
            }
            if (t1 >= 0) {
                int ts1 = ut_tilestart(t1);
                int tot1 = 32 * nw1;
                for (int i = tid; i < tot1; i += 1024) {
                    int rl = i / nw1, off = i - rl*nw1;
                    g_maskut[(size_t)b*UTW + ts1 + i] = tS1[rl][off];
                }
            }
        }
        __threadfence();
        __syncthreads();
    }

    // ======== stage C: last-arriving block runs nms ========
    if (tid == 0) s_old = (int)atomicAdd(&g_done[b], 1u);
    __syncthreads();
    if (s_old != 16) return;                  // not last: done
    __threadfence();                          // acquire all blocks' mask stores

    {
        unsigned* smu = (unsigned*)sraw;
        const uint4* mp4 = (const uint4*)&g_maskut[(size_t)b*UTW];
        uint4* sm4 = (uint4*)smu;
        __syncthreads();                      // smem reuse boundary
        for (int i = tid; i < UTW/4; i += 1024)
            sm4[i] = mp4[i];
        __syncthreads();

        if (tid < 32) {
            int lane = tid;
            unsigned alive = g_validw[b*32 + lane];
            int cnt = 0;
            unsigned bal = __ballot_sync(0xffffffffu, alive != 0u);
            while (cnt < MAXDET && bal) {
                int wp = __ffs(bal) - 1;
                int ts = ut_tilestart(wp);
                int nw = 32 - wp;
                unsigned curw = __shfl_sync(0xffffffffu, alive, wp);
                while (curw && cnt < MAXDET) {
                    int bit = __ffs(curw) - 1;
                    int rowoff = ts + bit * nw;
                    unsigned rw = smu[rowoff];
                    unsigned rl_w = (lane >= wp) ? smu[rowoff + lane - wp] : 0u;
                    curw &= ~rw;
                    curw &= ~(1u << bit);
                    alive &= ~rl_w;
                    if (lane == wp) alive &= ~(1u << bit);
                    if (lane == 0) g_sel[b*MAXDET + cnt] = wp*32 + bit;
                    cnt++;
                }
                bal = __ballot_sync(0xffffffffu, (lane > wp) && (alive != 0u));
            }
            if (lane == 0) {
                g_nk[b] = cnt;
                g_flag[b] = 0u;               // reset for next replay
                g_done[b] = 0u;
                __threadfence();
            }
        }
    }
}

// ---------------- phase 3: gather + emit output rows (unchanged R13) ----------------
__global__ void k_out(const float* __restrict__ pred,
                      const float* __restrict__ conf_logits,
                      const float* __restrict__ logits,
                      const float* __restrict__ head,
                      float* __restrict__ out) {
    int gw = (blockIdx.x * blockDim.x + threadIdx.x) >> 5;
    int lane = threadIdx.x & 31;
    if (gw >= BB*MAXDET) return;
    int b = gw / MAXDET, r = gw - b*MAXDET;
    size_t obase = (size_t)gw * OUTC;
    int nk = g_nk[b];
    if (r < nk) {
        int slot = g_sel[b*MAXDET + r];
        unsigned long long key = g_top[b*KPRE + slot];
        float score = __uint_as_float((unsigned)(key >> 32));
        unsigned anchor = (unsigned)key & 0x7FFFu;
        unsigned cls = ((unsigned)key >> 15) & 0x7Fu;
        size_t a = (size_t)b*NN + anchor;
        float objsig = 1.f / (1.f + expf(-conf_logits[a*5 + 4]));
        for (int c = lane; c < OUTC; c += 32) {
            float val;
            if (c < 4) {
                float x = pred[a*85], y = pred[a*85+1], w = pred[a*85+2], h = pred[a*85+3];
                val = (c == 0) ? x - w*0.5f : (c == 1) ? y - h*0.5f
                    : (c == 2) ? x + w*0.5f : y + h*0.5f;
            } else if (c == 4)  val = score;
            else if (c == 5)    val = (float)cls;
            else if (c < 86)    val = (1.f / (1.f + expf(-logits[a*80 + (c - 6)]))) * objsig;
            else if (c == 86)   val = objsig;
            else if (c == 87)   val = head[a];
            else                val = 1.f;
            out[obase + c] = val;
        }
    } else {
        for (int c = lane; c < OUTC; c += 32) out[obase + c] = 0.f;
    }
}

extern "C" void kernel_launch(void* const* d_in, const int* in_sizes, int n_in,
                              void* d_out, int out_size) {
    const float* pred = (const float*)d_in[0];
    const float* cl   = (const float*)d_in[1];
    const float* lg   = (const float*)d_in[2];
    const float* hd   = (const float*)d_in[3];
    float* out = (float*)d_out;

    cudaFuncSetAttribute(k_tail, cudaFuncAttributeMaxDynamicSharedMemorySize, SMTAIL);

    k_score<<<dim3(NN/APB, BB), 256>>>(pred);
    k_tail<<<dim3(17, BB), 1024, SMTAIL>>>(pred);
    k_out<<<(BB*MAXDET*32 + 255) / 256, 256>>>(pred, cl, lg, hd, out);
}

// round 15
// speedup vs baseline: 1.2570x; 1.2570x over previous
#include <cuda_runtime.h>
#include <cuda_bf16.h>
#include <math.h>

#define BB 16
#define NN 25200
#define KPRE 1024
#define MAXDET 300
#define OUTC 89
#define UTW 16896   // upper-triangle words per batch: 32 * 528
#define APB 24      // anchors per k_score block (NN % 24 == 0 -> 1050 blocks/batch)

// candidate key: [score_bits:32][(NN - anchor):15][class:7]
//   -> descending u64 order == (score desc, anchor asc); class never affects order.
// g_top entry:   [score_bits:32][class:7 @bit15][anchor:15 @bit0]

// ---------------- scratch (device globals; zero-initialized at load) ----------------
__device__ unsigned           g_cnt[BB];                 // zeroed at end of k_sortsel
__device__ unsigned long long g_cand[BB*NN];
__device__ unsigned long long g_top[BB*KPRE];
__device__ float4             g_boxes[BB*KPRE];
__device__ unsigned           g_validw[BB*32];
__device__ unsigned           g_maskut[BB*UTW];          // compacted upper-triangle mask
__device__ int                g_sel[BB*MAXDET];
__device__ int                g_nk[BB];

static __device__ __forceinline__ int score_bin(unsigned bits) {
    int bin = (int)(bits >> 16) - 0x3E00;
    return bin < 0 ? 0 : (bin > 511 ? 511 : bin);
}
static __device__ __forceinline__ int ut_tilestart(int t) {
    return 32 * (32*t - (t*(t-1))/2);
}
static __device__ __forceinline__ unsigned smem_u32(const void* p) {
    return (unsigned)__cvta_generic_to_shared(p);
}

// ---------------- phase 1: cp.async-staged score/argmax ----------------
// block = 256 threads, owns APB=24 consecutive anchors of one batch.
__global__ void k_score(const float* __restrict__ pred) {
    __shared__ __align__(16) float srow[APB*85];  // 2040 floats = 8160 B
    __shared__ unsigned long long sbuf[APB];
    __shared__ unsigned scnt;
    __shared__ unsigned sbase;
    int tid = threadIdx.x;
    int b = blockIdx.y;
    int a0 = blockIdx.x * APB;
    if (tid == 0) scnt = 0;

    // dense 16B-aligned gmem->smem staging, bypassing the register file:
    // 510 x cp.async.cg 16B per block (no STS, half the L1 wavefronts)
    {
        const uint4* gp = (const uint4*)(pred + ((size_t)b*NN + a0) * 85);
        unsigned sbase_addr = smem_u32(srow);
        #pragma unroll
        for (int i = tid; i < 510; i += 256) {
            asm volatile("cp.async.cg.shared.global [%0], [%1], 16;"
                         :: "r"(sbase_addr + i*16), "l"(gp + i));
        }
        asm volatile("cp.async.commit_group;");
        asm volatile("cp.async.wait_group 0;");
    }
    __syncthreads();

    int wid = tid >> 5, lane = tid & 31;
    #pragma unroll
    for (int k = 0; k < 3; k++) {
        int row = wid*3 + k;                     // 8 warps * 3 rows = 24
        const float* rp = &srow[row*85];
        float obj = rp[4];
        if (obj > 0.4f) {                        // warp-uniform (same smem word)
            float l0 = rp[lane];
            float l1 = rp[32 + lane];
            float l2 = (lane < 21) ? rp[64 + lane] : 0.f;
            // per-lane best in ascending class order; strict > keeps smallest class on ties
            float bv; int bi;
            if (lane >= 5) { bv = l0 * obj; bi = lane - 5; }     // classes 0..26
            else           { bv = -1.f;     bi = 127; }
            { float p = l1 * obj; if (p > bv) { bv = p; bi = 27 + lane; } }   // 27..58
            if (lane < 21) { float p = l2 * obj; if (p > bv) { bv = p; bi = 59 + lane; } } // 59..79

            unsigned u = __float_as_uint(bv);    // bv >= 0 after l1 step: bit order == float order
            unsigned mmax = __reduce_max_sync(0xffffffffu, u);
            unsigned mcls = __reduce_min_sync(0xffffffffu, (u == mmax) ? (unsigned)bi : 0xFFu);

            if (lane == 0 && __uint_as_float(mmax) > 0.4f) {
                unsigned anchor = (unsigned)(a0 + row);
                unsigned long long key = ((unsigned long long)mmax << 32)
                                       | ((unsigned long long)((unsigned)NN - anchor) << 7)
                                       | (unsigned long long)mcls;
                unsigned p = atomicAdd(&scnt, 1u);
                sbuf[p] = key;
            }
        }
    }
    __syncthreads();
    if (tid == 0 && scnt) sbase = atomicAdd(&g_cnt[b], scnt);
    __syncthreads();
    if (tid < scnt)
        g_cand[(size_t)b*NN + sbase + tid] = sbuf[tid];
}

// ---------------- phase 2: per-batch hist + exact threshold + T-bin sort + 1024 sort ----------------
__global__ void k_sortsel(const float* __restrict__ pred) {
    __shared__ unsigned long long skA[1024];
    __shared__ unsigned long long tbuf[4096];
    __shared__ unsigned hist[512];
    __shared__ int sT;
    __shared__ unsigned sM;
    __shared__ unsigned nA, nB;
    int b = blockIdx.x, tid = threadIdx.x;   // 1024 threads

    skA[tid] = 0ull;
    if (tid < 512) hist[tid] = 0u;
    if (tid == 0) { nA = 0; nB = 0; }
    __syncthreads();

    unsigned nc = min(g_cnt[b], (unsigned)NN);
    const unsigned long long* cand = &g_cand[(size_t)b*NN];
    for (unsigned i = tid; i < nc; i += 1024)
        atomicAdd(&hist[score_bin((unsigned)(cand[i] >> 32))], 1u);
    __syncthreads();
    for (int off = 1; off < 512; off <<= 1) {
        unsigned v = 0;
        if (tid < 512 && tid + off < 512) v = hist[tid + off];
        __syncthreads();
        if (tid < 512) hist[tid] += v;
        __syncthreads();
    }
    if (tid < 512) {
        unsigned suf  = hist[tid];
        unsigned sufn = (tid < 511) ? hist[tid + 1] : 0u;
        if (tid == 0 && suf < (unsigned)KPRE) { sT = -1; sM = 0; }
        if (suf >= (unsigned)KPRE && sufn < (unsigned)KPRE) { sT = tid; sM = suf - sufn; }
    }
    __syncthreads();
    int T = sT;
    unsigned m = min(sM, 4096u);                 // exact T-bin count (capped)
    unsigned St = 32; while (St < m) St <<= 1;   // sort width, known pre-scatter
    for (unsigned i = tid; i < St; i += 1024) tbuf[i] = 0ull;
    __syncthreads();
    for (unsigned i = tid; i < nc; i += 1024) {
        unsigned long long key = cand[i];
        int bin = score_bin((unsigned)(key >> 32));
        if (bin > T) {
            unsigned p = atomicAdd(&nA, 1u);
            if (p < 1024u) skA[p] = key;
        } else if (bin == T) {
            unsigned p = atomicAdd(&nB, 1u);
            if (p < 4096u) tbuf[p] = key;
        }
    }
    __syncthreads();
    if (m > 0u) {
        for (unsigned k2 = 2; k2 <= St; k2 <<= 1) {
            for (unsigned j = k2 >> 1; j > 0; j >>= 1) {
                for (unsigned i = tid; i < St; i += 1024) {
                    unsigned ixj = i ^ j;
                    if (ixj > i) {
                        bool up = ((i & k2) == 0);
                        unsigned long long x = tbuf[i], y = tbuf[ixj];
                        bool sw = up ? (x < y) : (x > y);
                        if (sw) { tbuf[i] = y; tbuf[ixj] = x; }
                    }
                }
                __syncthreads();
            }
        }
        unsigned a = nA;                 // < 1024 guaranteed by threshold choice
        unsigned needK = 1024u - a;
        if (tid < needK && tid < St) skA[a + tid] = tbuf[tid];
        __syncthreads();
    }
    for (unsigned k2 = 2; k2 <= 1024; k2 <<= 1) {
        for (unsigned j = k2 >> 1; j > 0; j >>= 1) {
            unsigned i = tid, ixj = i ^ j;
            if (ixj > i) {
                bool up = ((i & k2) == 0);
                unsigned long long x = skA[i], y = skA[ixj];
                bool sw = up ? (x < y) : (x > y);
                if (sw) { skA[i] = y; skA[ixj] = x; }
            }
            __syncthreads();
        }
    }
    // emit top-1024: repacked key, boxes, valid bits
    {
        unsigned long long key = skA[tid];
        unsigned bits = (unsigned)(key >> 32);
        unsigned anchor = 0, cls = 0;
        if (bits) {
            anchor = (unsigned)NN - ((unsigned)(key >> 7) & 0x7FFFu);
            cls = (unsigned)key & 0x7Fu;
        }
        g_top[b*KPRE + tid] = ((unsigned long long)bits << 32) | (cls << 15) | anchor;
        float4 bx = make_float4(0.f, 0.f, 0.f, 0.f);
        if (bits) {
            size_t pb = ((size_t)b*NN + anchor) * 85;
            float x = pred[pb], y = pred[pb+1], w = pred[pb+2], h = pred[pb+3];
            float off = (float)cls * 4096.0f;
            bx.x = (x - w*0.5f) + off;
            bx.y = (y - h*0.5f) + off;
            bx.z = (x + w*0.5f) + off;
            bx.w = (y + h*0.5f) + off;
        }
        g_boxes[b*KPRE + tid] = bx;
        unsigned bal = __ballot_sync(0xffffffffu, bits != 0u);
        if ((tid & 31) == 0) g_validw[b*32 + (tid >> 5)] = bal;
    }
    __syncthreads();
    if (tid == 0) g_cnt[b] = 0;   // reset for next replay
}

// ---------------- phase 3: IoU bit-mask, tile-pair packed blocks ----------------
__global__ void k_iou() {
    __shared__ float4 sb[1024];
    __shared__ float  sa[1024];
    __shared__ unsigned tS0[32][33];
    __shared__ unsigned tS1[32][33];
    int b = blockIdx.y, bx = blockIdx.x;
    int tid = threadIdx.x;
    float4 v = g_boxes[b*KPRE + tid];
    sb[tid] = v;
    sa[tid] = (v.z - v.x) * (v.w - v.y);
    __syncthreads();

    int t0 = bx;                         // bx=0..16
    int nw0 = 32 - t0;
    int t1 = (bx >= 1 && bx <= 15) ? 32 - bx : -1;
    int nw1 = (t1 >= 0) ? 32 - t1 : 0;

    int w = tid >> 5, lane = tid & 31;
    int tile = -1, wcol = 0;
    if (w < nw0)              { tile = t0; wcol = t0 + w; }
    else if (w < nw0 + nw1)   { tile = t1; wcol = t1 + (w - nw0); }

    if (tile >= 0) {
        int r = tile*32 + lane;
        float4 rb_ = sb[r];
        float  ra  = sa[r];
        unsigned bits = 0u;
        int j0 = wcol * 32;
        #pragma unroll 4
        for (int t = 0; t < 32; t++) {
            int j = j0 + t;
            float4 cb = sb[j];
            float ltx = fmaxf(rb_.x, cb.x), lty = fmaxf(rb_.y, cb.y);
            float rbx = fminf(rb_.z, cb.z), rby = fminf(rb_.w, cb.w);
            float iw = fmaxf(rbx - ltx, 0.f), ih = fmaxf(rby - lty, 0.f);
            float inter = iw * ih;
            float den = ((ra + sa[j]) - inter) + 1e-7f;
            float thr = 0.45f * den;
            bool sup;
            if (inter > thr * (1.0f + 1e-5f))       sup = true;
            else if (inter < thr * (1.0f - 1e-5f))  sup = false;
            else                                    sup = (__fdiv_rn(inter, den) > 0.45f);
            sup = sup && (j > r);
            bits |= sup ? (1u << t) : 0u;
        }
        if (tile == t0) tS0[lane][wcol - t0] = bits;
        else            tS1[lane][wcol - t1] = bits;
    }
    __syncthreads();
    {
        int ts0 = ut_tilestart(t0);
        int tot0 = 32 * nw0;
        for (int i = tid; i < tot0; i += 1024) {
            int rl = i / nw0, off = i - rl*nw0;
            g_maskut[(size_t)b*UTW + ts0 + i] = tS0[rl][off];
        }
        if (t1 >= 0) {
            int ts1 = ut_tilestart(t1);
            int tot1 = 32 * nw1;
            for (int i = tid; i < tot1; i += 1024) {
                int rl = i / nw1, off = i - rl*nw1;
                g_maskut[(size_t)b*UTW + ts1 + i] = tS1[rl][off];
            }
        }
    }
}

// ---------------- phase 4: greedy scan over compacted smem mask ----------------
__global__ void k_nms() {
    extern __shared__ unsigned smu[];           // UTW words = 66 KB
    int b = blockIdx.x, tid = threadIdx.x;      // 1024 threads
    const uint4* mp4 = (const uint4*)&g_maskut[(size_t)b*UTW];
    uint4* sm4 = (uint4*)smu;
    for (int i = tid; i < UTW/4; i += 1024)     // 4224 uint4
        sm4[i] = mp4[i];
    __syncthreads();

    if (tid < 32) {
        int lane = tid;
        unsigned alive = g_validw[b*32 + lane];   // lane holds indices [lane*32, lane*32+32)
        int cnt = 0;
        unsigned bal = __ballot_sync(0xffffffffu, alive != 0u);
        while (cnt < MAXDET && bal) {
            int wp = __ffs(bal) - 1;
            int ts = ut_tilestart(wp);
            int nw = 32 - wp;
            unsigned curw = __shfl_sync(0xffffffffu, alive, wp);
            while (curw && cnt < MAXDET) {
                int bit = __ffs(curw) - 1;
                int rowoff = ts + bit * nw;            // row i = wp*32+bit, words [wp,32)
                unsigned rw = smu[rowoff];             // broadcast: word wp of row i
                unsigned rl_w = (lane >= wp) ? smu[rowoff + lane - wp] : 0u;
                curw &= ~rw;
                curw &= ~(1u << bit);
                alive &= ~rl_w;
                if (lane == wp) alive &= ~(1u << bit);
                if (lane == 0) g_sel[b*MAXDET + cnt] = wp*32 + bit;
                cnt++;
            }
            bal = __ballot_sync(0xffffffffu, (lane > wp) && (alive != 0u));
        }
        if (lane == 0) g_nk[b] = cnt;
    }
}

// ---------------- phase 5: gather + emit output rows (wide) ----------------
__global__ void k_out(const float* __restrict__ pred,
                      const float* __restrict__ conf_logits,
                      const float* __restrict__ logits,
                      const float* __restrict__ head,
                      float* __restrict__ out) {
    int gw = (blockIdx.x * blockDim.x + threadIdx.x) >> 5;
    int lane = threadIdx.x & 31;
    if (gw >= BB*MAXDET) return;
    int b = gw / MAXDET, r = gw - b*MAXDET;
    size_t obase = (size_t)gw * OUTC;
    int nk = g_nk[b];
    if (r < nk) {
        int slot = g_sel[b*MAXDET + r];
        unsigned long long key = g_top[b*KPRE + slot];
        float score = __uint_as_float((unsigned)(key >> 32));
        unsigned anchor = (unsigned)key & 0x7FFFu;
        unsigned cls = ((unsigned)key >> 15) & 0x7Fu;
        size_t a = (size_t)b*NN + anchor;
        float objsig = 1.f / (1.f + expf(-conf_logits[a*5 + 4]));
        for (int c = lane; c < OUTC; c += 32) {
            float val;
            if (c < 4) {
                float x = pred[a*85], y = pred[a*85+1], w = pred[a*85+2], h = pred[a*85+3];
                val = (c == 0) ? x - w*0.5f : (c == 1) ? y - h*0.5f
                    : (c == 2) ? x + w*0.5f : y + h*0.5f;
            } else if (c == 4)  val = score;
            else if (c == 5)    val = (float)cls;
            else if (c < 86)    val = (1.f / (1.f + expf(-logits[a*80 + (c - 6)]))) * objsig;
            else if (c == 86)   val = objsig;
            else if (c == 87)   val = head[a];
            else                val = 1.f;
            out[obase + c] = val;
        }
    } else {
        for (int c = lane; c < OUTC; c += 32) out[obase + c] = 0.f;
    }
}

extern "C" void kernel_launch(void* const* d_in, const int* in_sizes, int n_in,
                              void* d_out, int out_size) {
    const float* pred = (const float*)d_in[0];
    const float* cl   = (const float*)d_in[1];
    const float* lg   = (const float*)d_in[2];
    const float* hd   = (const float*)d_in[3];
    float* out = (float*)d_out;

    cudaFuncSetAttribute(k_nms, cudaFuncAttributeMaxDynamicSharedMemorySize,
                         UTW * (int)sizeof(unsigned));

    k_score<<<dim3(NN/APB, BB), 256>>>(pred);   // 1050 x 16 blocks
    k_sortsel<<<BB, 1024>>>(pred);
    k_iou<<<dim3(17, BB), 1024>>>();            // tile-pair packed
    k_nms<<<BB, 1024, UTW * sizeof(unsigned)>>>();
    k_out<<<(BB*MAXDET*32 + 255) / 256, 256>>>(pred, cl, lg, hd, out);
}

// round 16
// speedup vs baseline: 1.3194x; 1.0497x over previous
#include <cuda_runtime.h>
#include <cuda_bf16.h>
#include <math.h>

#define BB 16
#define NN 25200
#define KPRE 1024
#define MAXDET 300
#define OUTC 89
#define UTW 16896   // upper-triangle words per batch: 32 * 528
#define APB 48      // anchors per k_score block, 2 stages of 24 (NN % 48 == 0 -> 525 blocks/batch)
#define HPB 24      // anchors per stage

// candidate key: [score_bits:32][(NN - anchor):15][class:7]
//   -> descending u64 order == (score desc, anchor asc); class never affects order.
// g_top entry:   [score_bits:32][class:7 @bit15][anchor:15 @bit0]

// ---------------- scratch (device globals; zero-initialized at load) ----------------
__device__ unsigned           g_cnt[BB];                 // zeroed at end of k_sortsel
__device__ unsigned long long g_cand[BB*NN];
__device__ unsigned long long g_top[BB*KPRE];
__device__ float4             g_boxes[BB*KPRE];
__device__ unsigned           g_validw[BB*32];
__device__ unsigned           g_maskut[BB*UTW];          // compacted upper-triangle mask
__device__ int                g_sel[BB*MAXDET];
__device__ int                g_nk[BB];

static __device__ __forceinline__ int score_bin(unsigned bits) {
    int bin = (int)(bits >> 16) - 0x3E00;
    return bin < 0 ? 0 : (bin > 511 ? 511 : bin);
}
static __device__ __forceinline__ int ut_tilestart(int t) {
    return 32 * (32*t - (t*(t-1))/2);
}
static __device__ __forceinline__ unsigned smem_u32(const void* p) {
    return (unsigned)__cvta_generic_to_shared(p);
}

// ---------------- phase 1: double-buffered cp.async score/argmax ----------------
// block = 256 threads, owns APB=48 consecutive anchors (2 stages x 24) of one batch.
__global__ void k_score(const float* __restrict__ pred) {
    __shared__ __align__(16) float srow[2][HPB*85];   // 2 x 8160 B
    __shared__ unsigned long long sbuf[APB];
    __shared__ unsigned scnt;
    __shared__ unsigned sbase;
    int tid = threadIdx.x;
    int b = blockIdx.y;
    int a0 = blockIdx.x * APB;
    if (tid == 0) scnt = 0;

    // issue BOTH stages' gmem->smem copies back-to-back (16 KB in flight/block)
    {
        const uint4* gp = (const uint4*)(pred + ((size_t)b*NN + a0) * 85);
        #pragma unroll
        for (int s = 0; s < 2; s++) {
            unsigned sa_ = smem_u32(srow[s]);
            const uint4* g = gp + s*510;
            #pragma unroll
            for (int i = tid; i < 510; i += 256) {
                asm volatile("cp.async.cg.shared.global [%0], [%1], 16;"
                             :: "r"(sa_ + i*16), "l"(g + i));
            }
            asm volatile("cp.async.commit_group;");
        }
    }

    int wid = tid >> 5, lane = tid & 31;
    #pragma unroll
    for (int s = 0; s < 2; s++) {
        if (s == 0) asm volatile("cp.async.wait_group 1;");   // stage 0 ready, stage 1 in flight
        else        asm volatile("cp.async.wait_group 0;");
        __syncthreads();
        #pragma unroll
        for (int k = 0; k < 3; k++) {
            int row = wid*3 + k;                     // 8 warps * 3 rows = 24
            const float* rp = &srow[s][row*85];
            float obj = rp[4];
            if (obj > 0.4f) {                        // warp-uniform (same smem word)
                float l0 = rp[lane];
                float l1 = rp[32 + lane];
                float l2 = (lane < 21) ? rp[64 + lane] : 0.f;
                // per-lane best in ascending class order; strict > keeps smallest class on ties
                float bv; int bi;
                if (lane >= 5) { bv = l0 * obj; bi = lane - 5; }     // classes 0..26
                else           { bv = -1.f;     bi = 127; }
                { float p = l1 * obj; if (p > bv) { bv = p; bi = 27 + lane; } }   // 27..58
                if (lane < 21) { float p = l2 * obj; if (p > bv) { bv = p; bi = 59 + lane; } } // 59..79

                unsigned u = __float_as_uint(bv);    // bv >= 0 after l1 step
                unsigned mmax = __reduce_max_sync(0xffffffffu, u);
                unsigned mcls = __reduce_min_sync(0xffffffffu, (u == mmax) ? (unsigned)bi : 0xFFu);

                if (lane == 0 && __uint_as_float(mmax) > 0.4f) {
                    unsigned anchor = (unsigned)(a0 + s*HPB + row);
                    unsigned long long key = ((unsigned long long)mmax << 32)
                                           | ((unsigned long long)((unsigned)NN - anchor) << 7)
                                           | (unsigned long long)mcls;
                    unsigned p = atomicAdd(&scnt, 1u);
                    sbuf[p] = key;
                }
            }
        }
    }
    __syncthreads();
    if (tid == 0 && scnt) sbase = atomicAdd(&g_cnt[b], scnt);
    __syncthreads();
    if (tid < scnt)
        g_cand[(size_t)b*NN + sbase + tid] = sbuf[tid];
}

// ---------------- phase 2: per-batch hist + exact threshold + T-bin sort + 1024 sort ----------------
__global__ void k_sortsel(const float* __restrict__ pred) {
    __shared__ unsigned long long skA[1024];
    __shared__ unsigned long long tbuf[4096];
    __shared__ unsigned hist[512];
    __shared__ int sT;
    __shared__ unsigned sM;
    __shared__ unsigned nA, nB;
    int b = blockIdx.x, tid = threadIdx.x;   // 1024 threads

    skA[tid] = 0ull;
    if (tid < 512) hist[tid] = 0u;
    if (tid == 0) { nA = 0; nB = 0; }
    __syncthreads();

    unsigned nc = min(g_cnt[b], (unsigned)NN);
    const unsigned long long* cand = &g_cand[(size_t)b*NN];
    for (unsigned i = tid; i < nc; i += 1024)
        atomicAdd(&hist[score_bin((unsigned)(cand[i] >> 32))], 1u);
    __syncthreads();
    for (int off = 1; off < 512; off <<= 1) {
        unsigned v = 0;
        if (tid < 512 && tid + off < 512) v = hist[tid + off];
        __syncthreads();
        if (tid < 512) hist[tid] += v;
        __syncthreads();
    }
    if (tid < 512) {
        unsigned suf  = hist[tid];
        unsigned sufn = (tid < 511) ? hist[tid + 1] : 0u;
        if (tid == 0 && suf < (unsigned)KPRE) { sT = -1; sM = 0; }
        if (suf >= (unsigned)KPRE && sufn < (unsigned)KPRE) { sT = tid; sM = suf - sufn; }
    }
    __syncthreads();
    int T = sT;
    unsigned m = min(sM, 4096u);                 // exact T-bin count (capped)
    unsigned St = 32; while (St < m) St <<= 1;   // sort width, known pre-scatter
    for (unsigned i = tid; i < St; i += 1024) tbuf[i] = 0ull;
    __syncthreads();
    for (unsigned i = tid; i < nc; i += 1024) {
        unsigned long long key = cand[i];
        int bin = score_bin((unsigned)(key >> 32));
        if (bin > T) {
            unsigned p = atomicAdd(&nA, 1u);
            if (p < 1024u) skA[p] = key;
        } else if (bin == T) {
            unsigned p = atomicAdd(&nB, 1u);
            if (p < 4096u) tbuf[p] = key;
        }
    }
    __syncthreads();
    if (m > 0u) {
        for (unsigned k2 = 2; k2 <= St; k2 <<= 1) {
            for (unsigned j = k2 >> 1; j > 0; j >>= 1) {
                for (unsigned i = tid; i < St; i += 1024) {
                    unsigned ixj = i ^ j;
                    if (ixj > i) {
                        bool up = ((i & k2) == 0);
                        unsigned long long x = tbuf[i], y = tbuf[ixj];
                        bool sw = up ? (x < y) : (x > y);
                        if (sw) { tbuf[i] = y; tbuf[ixj] = x; }
                    }
                }
                __syncthreads();
            }
        }
        unsigned a = nA;                 // < 1024 guaranteed by threshold choice
        unsigned needK = 1024u - a;
        if (tid < needK && tid < St) skA[a + tid] = tbuf[tid];
        __syncthreads();
    }
    for (unsigned k2 = 2; k2 <= 1024; k2 <<= 1) {
        for (unsigned j = k2 >> 1; j > 0; j >>= 1) {
            unsigned i = tid, ixj = i ^ j;
            if (ixj > i) {
                bool up = ((i & k2) == 0);
                unsigned long long x = skA[i], y = skA[ixj];
                bool sw = up ? (x < y) : (x > y);
                if (sw) { skA[i] = y; skA[ixj] = x; }
            }
            __syncthreads();
        }
    }
    // emit top-1024: repacked key, boxes, valid bits
    {
        unsigned long long key = skA[tid];
        unsigned bits = (unsigned)(key >> 32);
        unsigned anchor = 0, cls = 0;
        if (bits) {
            anchor = (unsigned)NN - ((unsigned)(key >> 7) & 0x7FFFu);
            cls = (unsigned)key & 0x7Fu;
        }
        g_top[b*KPRE + tid] = ((unsigned long long)bits << 32) | (cls << 15) | anchor;
        float4 bx = make_float4(0.f, 0.f, 0.f, 0.f);
        if (bits) {
            size_t pb = ((size_t)b*NN + anchor) * 85;
            float x = pred[pb], y = pred[pb+1], w = pred[pb+2], h = pred[pb+3];
            float off = (float)cls * 4096.0f;
            bx.x = (x - w*0.5f) + off;
            bx.y = (y - h*0.5f) + off;
            bx.z = (x + w*0.5f) + off;
            bx.w = (y + h*0.5f) + off;
        }
        g_boxes[b*KPRE + tid] = bx;
        unsigned bal = __ballot_sync(0xffffffffu, bits != 0u);
        if ((tid & 31) == 0) g_validw[b*32 + (tid >> 5)] = bal;
    }
    __syncthreads();
    if (tid == 0) g_cnt[b] = 0;   // reset for next replay
}

// ---------------- phase 3: IoU bit-mask, tile-pair packed blocks ----------------
__global__ void k_iou() {
    __shared__ float4 sb[1024];
    __shared__ float  sa[1024];
    __shared__ unsigned tS0[32][33];
    __shared__ unsigned tS1[32][33];
    int b = blockIdx.y, bx = blockIdx.x;
    int tid = threadIdx.x;
    float4 v = g_boxes[b*KPRE + tid];
    sb[tid] = v;
    sa[tid] = (v.z - v.x) * (v.w - v.y);
    __syncthreads();

    int t0 = bx;                         // bx=0..16
    int nw0 = 32 - t0;
    int t1 = (bx >= 1 && bx <= 15) ? 32 - bx : -1;
    int nw1 = (t1 >= 0) ? 32 - t1 : 0;

    int w = tid >> 5, lane = tid & 31;
    int tile = -1, wcol = 0;
    if (w < nw0)              { tile = t0; wcol = t0 + w; }
    else if (w < nw0 + nw1)   { tile = t1; wcol = t1 + (w - nw0); }

    if (tile >= 0) {
        int r = tile*32 + lane;
        float4 rb_ = sb[r];
        float  ra  = sa[r];
        unsigned bits = 0u;
        int j0 = wcol * 32;
        #pragma unroll 4
        for (int t = 0; t < 32; t++) {
            int j = j0 + t;
            float4 cb = sb[j];
            float ltx = fmaxf(rb_.x, cb.x), lty = fmaxf(rb_.y, cb.y);
            float rbx = fminf(rb_.z, cb.z), rby = fminf(rb_.w, cb.w);
            float iw = fmaxf(rbx - ltx, 0.f), ih = fmaxf(rby - lty, 0.f);
            float inter = iw * ih;
            float den = ((ra + sa[j]) - inter) + 1e-7f;
            float thr = 0.45f * den;
            bool sup;
            if (inter > thr * (1.0f + 1e-5f))       sup = true;
            else if (inter < thr * (1.0f - 1e-5f))  sup = false;
            else                                    sup = (__fdiv_rn(inter, den) > 0.45f);
            sup = sup && (j > r);
            bits |= sup ? (1u << t) : 0u;
        }
        if (tile == t0) tS0[lane][wcol - t0] = bits;
        else            tS1[lane][wcol - t1] = bits;
    }
    __syncthreads();
    {
        int ts0 = ut_tilestart(t0);
        int tot0 = 32 * nw0;
        for (int i = tid; i < tot0; i += 1024) {
            int rl = i / nw0, off = i - rl*nw0;
            g_maskut[(size_t)b*UTW + ts0 + i] = tS0[rl][off];
        }
        if (t1 >= 0) {
            int ts1 = ut_tilestart(t1);
            int tot1 = 32 * nw1;
            for (int i = tid; i < tot1; i += 1024) {
                int rl = i / nw1, off = i - rl*nw1;
                g_maskut[(size_t)b*UTW + ts1 + i] = tS1[rl][off];
            }
        }
    }
}

// ---------------- phase 4: greedy scan over compacted smem mask ----------------
__global__ void k_nms() {
    extern __shared__ unsigned smu[];           // UTW words = 66 KB
    int b = blockIdx.x, tid = threadIdx.x;      // 1024 threads
    const uint4* mp4 = (const uint4*)&g_maskut[(size_t)b*UTW];
    uint4* sm4 = (uint4*)smu;
    for (int i = tid; i < UTW/4; i += 1024)     // 4224 uint4
        sm4[i] = mp4[i];
    __syncthreads();

    if (tid < 32) {
        int lane = tid;
        unsigned alive = g_validw[b*32 + lane];   // lane holds indices [lane*32, lane*32+32)
        int cnt = 0;
        unsigned bal = __ballot_sync(0xffffffffu, alive != 0u);
        while (cnt < MAXDET && bal) {
            int wp = __ffs(bal) - 1;
            int ts = ut_tilestart(wp);
            int nw = 32 - wp;
            unsigned curw = __shfl_sync(0xffffffffu, alive, wp);
            while (curw && cnt < MAXDET) {
                int bit = __ffs(curw) - 1;
                int rowoff = ts + bit * nw;            // row i = wp*32+bit, words [wp,32)
                unsigned rw = smu[rowoff];             // broadcast: word wp of row i
                unsigned rl_w = (lane >= wp) ? smu[rowoff + lane - wp] : 0u;
                curw &= ~rw;
                curw &= ~(1u << bit);
                alive &= ~rl_w;
                if (lane == wp) alive &= ~(1u << bit);
                if (lane == 0) g_sel[b*MAXDET + cnt] = wp*32 + bit;
                cnt++;
            }
            bal = __ballot_sync(0xffffffffu, (lane > wp) && (alive != 0u));
        }
        if (lane == 0) g_nk[b] = cnt;
    }
}

// ---------------- phase 5: gather + emit output rows (wide) ----------------
__global__ void k_out(const float* __restrict__ pred,
                      const float* __restrict__ conf_logits,
                      const float* __restrict__ logits,
                      const float* __restrict__ head,
                      float* __restrict__ out) {
    int gw = (blockIdx.x * blockDim.x + threadIdx.x) >> 5;
    int lane = threadIdx.x & 31;
    if (gw >= BB*MAXDET) return;
    int b = gw / MAXDET, r = gw - b*MAXDET;
    size_t obase = (size_t)gw * OUTC;
    int nk = g_nk[b];
    if (r < nk) {
        int slot = g_sel[b*MAXDET + r];
        unsigned long long key = g_top[b*KPRE + slot];
        float score = __uint_as_float((unsigned)(key >> 32));
        unsigned anchor = (unsigned)key & 0x7FFFu;
        unsigned cls = ((unsigned)key >> 15) & 0x7Fu;
        size_t a = (size_t)b*NN + anchor;
        float objsig = 1.f / (1.f + expf(-conf_logits[a*5 + 4]));
        for (int c = lane; c < OUTC; c += 32) {
            float val;
            if (c < 4) {
                float x = pred[a*85], y = pred[a*85+1], w = pred[a*85+2], h = pred[a*85+3];
                val = (c == 0) ? x - w*0.5f : (c == 1) ? y - h*0.5f
                    : (c == 2) ? x + w*0.5f : y + h*0.5f;
            } else if (c == 4)  val = score;
            else if (c == 5)    val = (float)cls;
            else if (c < 86)    val = (1.f / (1.f + expf(-logits[a*80 + (c - 6)]))) * objsig;
            else if (c == 86)   val = objsig;
            else if (c == 87)   val = head[a];
            else                val = 1.f;
            out[obase + c] = val;
        }
    } else {
        for (int c = lane; c < OUTC; c += 32) out[obase + c] = 0.f;
    }
}

extern "C" void kernel_launch(void* const* d_in, const int* in_sizes, int n_in,
                              void* d_out, int out_size) {
    const float* pred = (const float*)d_in[0];
    const float* cl   = (const float*)d_in[1];
    const float* lg   = (const float*)d_in[2];
    const float* hd   = (const float*)d_in[3];
    float* out = (float*)d_out;

    cudaFuncSetAttribute(k_nms, cudaFuncAttributeMaxDynamicSharedMemorySize,
                         UTW * (int)sizeof(unsigned));

    k_score<<<dim3(NN/APB, BB), 256>>>(pred);   // 525 x 16 blocks, double-buffered
    k_sortsel<<<BB, 1024>>>(pred);
    k_iou<<<dim3(17, BB), 1024>>>();            // tile-pair packed
    k_nms<<<BB, 1024, UTW * sizeof(unsigned)>>>();
    k_out<<<(BB*MAXDET*32 + 255) / 256, 256>>>(pred, cl, lg, hd, out);
}

// round 17
// speedup vs baseline: 1.4712x; 1.1150x over previous
#include <cuda_runtime.h>
#include <cuda_bf16.h>
#include <math.h>

#define BB 16
#define NN 25200
#define KPRE 1024
#define MAXDET 300
#define OUTC 89
#define UTW 16896   // upper-triangle words per batch: 32 * 528
#define APB 48      // anchors per k_score block, 2 stages of 24
#define HPB 24      // anchors per stage

// candidate key: [score_bits:32][(NN - anchor):15][class:7]
// g_top entry:   [score_bits:32][class:7 @bit15][anchor:15 @bit0]

// ---------------- scratch (device globals; zero-initialized at load) ----------------
__device__ unsigned           g_cnt[BB];                 // zeroed at end of k_sortsel
__device__ unsigned long long g_cand[BB*NN];
__device__ unsigned long long g_top[BB*KPRE];
__device__ float4             g_boxes[BB*KPRE];
__device__ unsigned           g_validw[BB*32];
__device__ unsigned           g_maskut[BB*UTW];          // compacted upper-triangle mask
__device__ int                g_sel[BB*MAXDET];
__device__ int                g_nk[BB];

static __device__ __forceinline__ int score_bin(unsigned bits) {
    int bin = (int)(bits >> 16) - 0x3E00;
    return bin < 0 ? 0 : (bin > 511 ? 511 : bin);
}
static __device__ __forceinline__ int ut_tilestart(int t) {
    return 32 * (32*t - (t*(t-1))/2);
}
static __device__ __forceinline__ unsigned smem_u32(const void* p) {
    return (unsigned)__cvta_generic_to_shared(p);
}

// ---------------- phase 1: double-buffered cp.async score/argmax (unchanged R16) ----------------
__global__ void k_score(const float* __restrict__ pred) {
    __shared__ __align__(16) float srow[2][HPB*85];
    __shared__ unsigned long long sbuf[APB];
    __shared__ unsigned scnt;
    __shared__ unsigned sbase;
    int tid = threadIdx.x;
    int b = blockIdx.y;
    int a0 = blockIdx.x * APB;
    if (tid == 0) scnt = 0;

    {
        const uint4* gp = (const uint4*)(pred + ((size_t)b*NN + a0) * 85);
        #pragma unroll
        for (int s = 0; s < 2; s++) {
            unsigned sa_ = smem_u32(srow[s]);
            const uint4* g = gp + s*510;
            #pragma unroll
            for (int i = tid; i < 510; i += 256) {
                asm volatile("cp.async.cg.shared.global [%0], [%1], 16;"
                             :: "r"(sa_ + i*16), "l"(g + i));
            }
            asm volatile("cp.async.commit_group;");
        }
    }

    int wid = tid >> 5, lane = tid & 31;
    #pragma unroll
    for (int s = 0; s < 2; s++) {
        if (s == 0) asm volatile("cp.async.wait_group 1;");
        else        asm volatile("cp.async.wait_group 0;");
        __syncthreads();
        #pragma unroll
        for (int k = 0; k < 3; k++) {
            int row = wid*3 + k;
            const float* rp = &srow[s][row*85];
            float obj = rp[4];
            if (obj > 0.4f) {
                float l0 = rp[lane];
                float l1 = rp[32 + lane];
                float l2 = (lane < 21) ? rp[64 + lane] : 0.f;
                float bv; int bi;
                if (lane >= 5) { bv = l0 * obj; bi = lane - 5; }
                else           { bv = -1.f;     bi = 127; }
                { float p = l1 * obj; if (p > bv) { bv = p; bi = 27 + lane; } }
                if (lane < 21) { float p = l2 * obj; if (p > bv) { bv = p; bi = 59 + lane; } }

                unsigned u = __float_as_uint(bv);
                unsigned mmax = __reduce_max_sync(0xffffffffu, u);
                unsigned mcls = __reduce_min_sync(0xffffffffu, (u == mmax) ? (unsigned)bi : 0xFFu);

                if (lane == 0 && __uint_as_float(mmax) > 0.4f) {
                    unsigned anchor = (unsigned)(a0 + s*HPB + row);
                    unsigned long long key = ((unsigned long long)mmax << 32)
                                           | ((unsigned long long)((unsigned)NN - anchor) << 7)
                                           | (unsigned long long)mcls;
                    unsigned p = atomicAdd(&scnt, 1u);
                    sbuf[p] = key;
                }
            }
        }
    }
    __syncthreads();
    if (tid == 0 && scnt) sbase = atomicAdd(&g_cnt[b], scnt);
    __syncthreads();
    if (tid < scnt)
        g_cand[(size_t)b*NN + sbase + tid] = sbuf[tid];
}

// ---------------- phase 2: per-batch hist + exact threshold + T-bin sort + 1024 sort ----------------
__global__ void k_sortsel(const float* __restrict__ pred) {
    __shared__ unsigned long long skA[1024];
    __shared__ unsigned long long tbuf[4096];
    __shared__ unsigned hist[512];
    __shared__ int sT;
    __shared__ unsigned sM;
    __shared__ unsigned nA, nB;
    int b = blockIdx.x, tid = threadIdx.x;

    skA[tid] = 0ull;
    if (tid < 512) hist[tid] = 0u;
    if (tid == 0) { nA = 0; nB = 0; }
    __syncthreads();

    unsigned nc = min(g_cnt[b], (unsigned)NN);
    const unsigned long long* cand = &g_cand[(size_t)b*NN];
    for (unsigned i = tid; i < nc; i += 1024)
        atomicAdd(&hist[score_bin((unsigned)(cand[i] >> 32))], 1u);
    __syncthreads();
    for (int off = 1; off < 512; off <<= 1) {
        unsigned v = 0;
        if (tid < 512 && tid + off < 512) v = hist[tid + off];
        __syncthreads();
        if (tid < 512) hist[tid] += v;
        __syncthreads();
    }
    if (tid < 512) {
        unsigned suf  = hist[tid];
        unsigned sufn = (tid < 511) ? hist[tid + 1] : 0u;
        if (tid == 0 && suf < (unsigned)KPRE) { sT = -1; sM = 0; }
        if (suf >= (unsigned)KPRE && sufn < (unsigned)KPRE) { sT = tid; sM = suf - sufn; }
    }
    __syncthreads();
    int T = sT;
    unsigned m = min(sM, 4096u);
    unsigned St = 32; while (St < m) St <<= 1;
    for (unsigned i = tid; i < St; i += 1024) tbuf[i] = 0ull;
    __syncthreads();
    for (unsigned i = tid; i < nc; i += 1024) {
        unsigned long long key = cand[i];
        int bin = score_bin((unsigned)(key >> 32));
        if (bin > T) {
            unsigned p = atomicAdd(&nA, 1u);
            if (p < 1024u) skA[p] = key;
        } else if (bin == T) {
            unsigned p = atomicAdd(&nB, 1u);
            if (p < 4096u) tbuf[p] = key;
        }
    }
    __syncthreads();
    if (m > 0u) {
        for (unsigned k2 = 2; k2 <= St; k2 <<= 1) {
            for (unsigned j = k2 >> 1; j > 0; j >>= 1) {
                for (unsigned i = tid; i < St; i += 1024) {
                    unsigned ixj = i ^ j;
                    if (ixj > i) {
                        bool up = ((i & k2) == 0);
                        unsigned long long x = tbuf[i], y = tbuf[ixj];
                        bool sw = up ? (x < y) : (x > y);
                        if (sw) { tbuf[i] = y; tbuf[ixj] = x; }
                    }
                }
                __syncthreads();
            }
        }
        unsigned a = nA;
        unsigned needK = 1024u - a;
        if (tid < needK && tid < St) skA[a + tid] = tbuf[tid];
        __syncthreads();
    }
    for (unsigned k2 = 2; k2 <= 1024; k2 <<= 1) {
        for (unsigned j = k2 >> 1; j > 0; j >>= 1) {
            unsigned i = tid, ixj = i ^ j;
            if (ixj > i) {
                bool up = ((i & k2) == 0);
                unsigned long long x = skA[i], y = skA[ixj];
                bool sw = up ? (x < y) : (x > y);
                if (sw) { skA[i] = y; skA[ixj] = x; }
            }
            __syncthreads();
        }
    }
    {
        unsigned long long key = skA[tid];
        unsigned bits = (unsigned)(key >> 32);
        unsigned anchor = 0, cls = 0;
        if (bits) {
            anchor = (unsigned)NN - ((unsigned)(key >> 7) & 0x7FFFu);
            cls = (unsigned)key & 0x7Fu;
        }
        g_top[b*KPRE + tid] = ((unsigned long long)bits << 32) | (cls << 15) | anchor;
        float4 bx = make_float4(0.f, 0.f, 0.f, 0.f);
        if (bits) {
            size_t pb = ((size_t)b*NN + anchor) * 85;
            float x = pred[pb], y = pred[pb+1], w = pred[pb+2], h = pred[pb+3];
            float off = (float)cls * 4096.0f;
            bx.x = (x - w*0.5f) + off;
            bx.y = (y - h*0.5f) + off;
            bx.z = (x + w*0.5f) + off;
            bx.w = (y + h*0.5f) + off;
        }
        g_boxes[b*KPRE + tid] = bx;
        unsigned bal = __ballot_sync(0xffffffffu, bits != 0u);
        if ((tid & 31) == 0) g_validw[b*32 + (tid >> 5)] = bal;
    }
    __syncthreads();
    if (tid == 0) g_cnt[b] = 0;
}

// ---------------- phase 3: IoU bit-mask, tile-pair packed blocks (unchanged R16) ----------------
__global__ void k_iou() {
    __shared__ float4 sb[1024];
    __shared__ float  sa[1024];
    __shared__ unsigned tS0[32][33];
    __shared__ unsigned tS1[32][33];
    int b = blockIdx.y, bx = blockIdx.x;
    int tid = threadIdx.x;
    float4 v = g_boxes[b*KPRE + tid];
    sb[tid] = v;
    sa[tid] = (v.z - v.x) * (v.w - v.y);
    __syncthreads();

    int t0 = bx;
    int nw0 = 32 - t0;
    int t1 = (bx >= 1 && bx <= 15) ? 32 - bx : -1;
    int nw1 = (t1 >= 0) ? 32 - t1 : 0;

    int w = tid >> 5, lane = tid & 31;
    int tile = -1, wcol = 0;
    if (w < nw0)              { tile = t0; wcol = t0 + w; }
    else if (w < nw0 + nw1)   { tile = t1; wcol = t1 + (w - nw0); }

    if (tile >= 0) {
        int r = tile*32 + lane;
        float4 rb_ = sb[r];
        float  ra  = sa[r];
        unsigned bits = 0u;
        int j0 = wcol * 32;
        #pragma unroll 4
        for (int t = 0; t < 32; t++) {
            int j = j0 + t;
            float4 cb = sb[j];
            float ltx = fmaxf(rb_.x, cb.x), lty = fmaxf(rb_.y, cb.y);
            float rbx = fminf(rb_.z, cb.z), rby = fminf(rb_.w, cb.w);
            float iw = fmaxf(rbx - ltx, 0.f), ih = fmaxf(rby - lty, 0.f);
            float inter = iw * ih;
            float den = ((ra + sa[j]) - inter) + 1e-7f;
            float thr = 0.45f * den;
            bool sup;
            if (inter > thr * (1.0f + 1e-5f))       sup = true;
            else if (inter < thr * (1.0f - 1e-5f))  sup = false;
            else                                    sup = (__fdiv_rn(inter, den) > 0.45f);
            sup = sup && (j > r);
            bits |= sup ? (1u << t) : 0u;
        }
        if (tile == t0) tS0[lane][wcol - t0] = bits;
        else            tS1[lane][wcol - t1] = bits;
    }
    __syncthreads();
    {
        int ts0 = ut_tilestart(t0);
        int tot0 = 32 * nw0;
        for (int i = tid; i < tot0; i += 1024) {
            int rl = i / nw0, off = i - rl*nw0;
            g_maskut[(size_t)b*UTW + ts0 + i] = tS0[rl][off];
        }
        if (t1 >= 0) {
            int ts1 = ut_tilestart(t1);
            int tot1 = 32 * nw1;
            for (int i = tid; i < tot1; i += 1024) {
                int rl = i / nw1, off = i - rl*nw1;
                g_maskut[(size_t)b*UTW + ts1 + i] = tS1[rl][off];
            }
        }
    }
}

// ---------------- phase 4: Jacobi-fixpoint greedy NMS ----------------
// keep[i] = valid[i] && !any(j<i kept && sup[j,i]); iterate keep' = valid & ~OR(kept rows)
// until no change -> exact greedy fixpoint. Depth bounded by per-class chain length (~13).
__global__ void k_nms() {
    extern __shared__ unsigned smu[];           // UTW words = 66 KB
    __shared__ unsigned ssupp[32][33];
    __shared__ unsigned skeep[32], svalid[32];
    __shared__ int schanged;
    int b = blockIdx.x, tid = threadIdx.x;      // 1024 threads = 32 warps
    int wid = tid >> 5, lane = tid & 31;

    const uint4* mp4 = (const uint4*)&g_maskut[(size_t)b*UTW];
    uint4* sm4 = (uint4*)smu;
    for (int i = tid; i < UTW/4; i += 1024)
        sm4[i] = mp4[i];
    if (tid < 32) {
        unsigned v = g_validw[b*32 + tid];
        svalid[tid] = v;
        skeep[tid] = v;
    }
    __syncthreads();

    int ts = ut_tilestart(wid);
    int nw = 32 - wid;
    int off = lane - wid;
    for (int it = 0; it < 1025; it++) {
        // warp g ORs the mask rows of its kept candidates [g*32, g*32+32)
        unsigned kw = skeep[wid];               // broadcast
        unsigned val = 0u;
        if (lane >= wid) {
            unsigned kk = kw;
            while (kk) {
                int k = __ffs(kk) - 1; kk &= kk - 1u;
                val |= smu[ts + k*nw + off];
            }
        }
        ssupp[wid][lane] = val;
        __syncthreads();
        // warp 0: column-OR across warps, new keep, convergence check
        if (tid < 32) {
            unsigned s = 0u;
            #pragma unroll
            for (int g = 0; g < 32; g++) s |= ssupp[g][tid];
            unsigned nk2 = svalid[tid] & ~s;
            unsigned ch = __ballot_sync(0xffffffffu, nk2 != skeep[tid]);
            skeep[tid] = nk2;
            if (tid == 0) schanged = (ch != 0u);
        }
        __syncthreads();
        if (!schanged) break;
    }

    // enumerate first <=300 kept indices in order
    if (tid < 32) {
        unsigned kw = skeep[tid];
        int pc = __popc(kw);
        int pre = pc;
        #pragma unroll
        for (int o = 1; o < 32; o <<= 1) {
            int v = __shfl_up_sync(0xffffffffu, pre, o);
            if (lane >= o) pre += v;
        }
        int total = __shfl_sync(0xffffffffu, pre, 31);
        pre -= pc;                              // exclusive prefix
        unsigned kk = kw; int r = pre;
        while (kk) {
            int k = __ffs(kk) - 1; kk &= kk - 1u;
            if (r < MAXDET) g_sel[b*MAXDET + r] = tid*32 + k;
            r++;
        }
        if (lane == 0) g_nk[b] = total < MAXDET ? total : MAXDET;
    }
}

// ---------------- phase 5: gather + emit output rows (unchanged) ----------------
__global__ void k_out(const float* __restrict__ pred,
                      const float* __restrict__ conf_logits,
                      const float* __restrict__ logits,
                      const float* __restrict__ head,
                      float* __restrict__ out) {
    int gw = (blockIdx.x * blockDim.x + threadIdx.x) >> 5;
    int lane = threadIdx.x & 31;
    if (gw >= BB*MAXDET) return;
    int b = gw / MAXDET, r = gw - b*MAXDET;
    size_t obase = (size_t)gw * OUTC;
    int nk = g_nk[b];
    if (r < nk) {
        int slot = g_sel[b*MAXDET + r];
        unsigned long long key = g_top[b*KPRE + slot];
        float score = __uint_as_float((unsigned)(key >> 32));
        unsigned anchor = (unsigned)key & 0x7FFFu;
        unsigned cls = ((unsigned)key >> 15) & 0x7Fu;
        size_t a = (size_t)b*NN + anchor;
        float objsig = 1.f / (1.f + expf(-conf_logits[a*5 + 4]));
        for (int c = lane; c < OUTC; c += 32) {
            float val;
            if (c < 4) {
                float x = pred[a*85], y = pred[a*85+1], w = pred[a*85+2], h = pred[a*85+3];
                val = (c == 0) ? x - w*0.5f : (c == 1) ? y - h*0.5f
                    : (c == 2) ? x + w*0.5f : y + h*0.5f;
            } else if (c == 4)  val = score;
            else if (c == 5)    val = (float)cls;
            else if (c < 86)    val = (1.f / (1.f + expf(-logits[a*80 + (c - 6)]))) * objsig;
            else if (c == 86)   val = objsig;
            else if (c == 87)   val = head[a];
            else                val = 1.f;
            out[obase + c] = val;
        }
    } else {
        for (int c = lane; c < OUTC; c += 32) out[obase + c] = 0.f;
    }
}

extern "C" void kernel_launch(void* const* d_in, const int* in_sizes, int n_in,
                              void* d_out, int out_size) {
    const float* pred = (const float*)d_in[0];
    const float* cl   = (const float*)d_in[1];
    const float* lg   = (const float*)d_in[2];
    const float* hd   = (const float*)d_in[3];
    float* out = (float*)d_out;

    cudaFuncSetAttribute(k_nms, cudaFuncAttributeMaxDynamicSharedMemorySize,
                         UTW * (int)sizeof(unsigned));

    k_score<<<dim3(NN/APB, BB), 256>>>(pred);   // 525 x 16 blocks, double-buffered
    k_sortsel<<<BB, 1024>>>(pred);
    k_iou<<<dim3(17, BB), 1024>>>();            // tile-pair packed
    k_nms<<<BB, 1024, UTW * sizeof(unsigned)>>>();
    k_out<<<(BB*MAXDET*32 + 255) / 256, 256>>>(pred, cl, lg, hd, out);
}